// round 8
// baseline (speedup 1.0000x reference)
#include <cuda_runtime.h>
#include <math.h>
#include <stdint.h>

#define Ldim 128
#define Ddim 512
#define Mdim 2048
#define NTAIL 127

__device__ float g_A[Ldim*Ddim];
__device__ float g_Ah[Ldim*Ddim];
__device__ float g_Al[Ldim*Ddim];
__device__ float g_Bm[Ldim*Ddim];
__device__ float g_T[Ldim*Mdim];
__device__ float g_Uh[Ldim*Mdim];
__device__ float g_Ul[Ldim*Mdim];
__device__ float g_xh[Ddim*Mdim];
__device__ float g_xl[Ddim*Mdim];
__device__ float g_G[5][Ldim*Ddim];
__device__ float g_S[Ddim*Ddim];
__device__ float g_P0[Ddim*Ddim];
__device__ float g_P1[Ddim*Ddim];
__device__ float g_Delta[Ldim*Ldim];
__device__ float g_DtD[Ldim*Ldim];
__device__ float g_DtDh[Ldim*Ldim];
__device__ float g_DtDl[Ldim*Ldim];
__device__ float g_Q0[Ldim*Ldim];
__device__ float g_Q1[Ldim*Ldim];
__device__ float g_ytail[NTAIL];
__device__ float g_red[4];
__device__ float g_scal[4];   // [0]=maxeig(xxT) [1]=maxeig(DtD) [2]=tau [3]=thr
__device__ int   g_done;

// ---------------- helpers ----------------
__device__ __forceinline__ float tf32_rna(float v) {
    uint32_t r;
    asm("cvt.rna.tf32.f32 %0, %1;" : "=r"(r) : "f"(v));
    return __uint_as_float(r);
}

// D(16x8,f32) += A(16x8 row-major tf32) * B(8x8 col-major tf32)
// a0=A[m][k] a1=A[m+8][k] a2=A[m][k+4] a3=A[m+8][k+4]; b0=B[k][n] b1=B[k+4][n]
__device__ __forceinline__ void mma8(float* d, float2 a0, float2 a1, float2 b) {
    asm volatile(
        "mma.sync.aligned.m16n8k8.row.col.f32.tf32.tf32.f32 "
        "{%0,%1,%2,%3},{%4,%5,%6,%7},{%8,%9},{%0,%1,%2,%3};"
        : "+f"(d[0]), "+f"(d[1]), "+f"(d[2]), "+f"(d[3])
        : "r"(__float_as_uint(a0.x)), "r"(__float_as_uint(a1.x)),
          "r"(__float_as_uint(a0.y)), "r"(__float_as_uint(a1.y)),
          "r"(__float_as_uint(b.x)),  "r"(__float_as_uint(b.y)));
}

// smem slot permutation within an 8-wide k-group: k and k+4 adjacent
#define SLOT(c) (((c) >> 3) * 8 + 2 * ((c) & 3) + (((c) & 7) >> 2))

// ---------------- init / constants ----------------
__global__ void k_init(const float* __restrict__ mask, const float* __restrict__ py,
                       const float* __restrict__ y0) {
    int idx = blockIdx.x * blockDim.x + threadIdx.x;
    if (idx < Ldim*Ddim) { g_A[idx] = 0.f; g_Bm[idx] = 0.f; g_Ah[idx] = 0.f; g_Al[idx] = 0.f; }
    if (idx < Ldim*Mdim) {
        float u = -mask[idx] * py[idx];
        float h = tf32_rna(u);
        g_Uh[idx] = h;
        g_Ul[idx] = tf32_rna(u - h);
    }
    if (idx < NTAIL) { g_ytail[idx] = y0[Mdim + idx]; }
    if (idx == 0)    { g_done = 0; }
}

__global__ void k_xsplit(const float* __restrict__ x) {
    int idx = blockIdx.x * blockDim.x + threadIdx.x;
    if (idx < Ddim*Mdim) {
        float v = x[idx];
        float h = tf32_rna(v);
        g_xh[idx] = h;
        g_xl[idx] = tf32_rna(v - h);
    }
}

__global__ void k_delta() {
    int idx = blockIdx.x * blockDim.x + threadIdx.x;
    if (idx < Ldim*Ldim) {
        int p = idx >> 7, c = idx & 127;
        float v = (c == p) ? 1.f : ((c == p-1) ? -2.f : ((c == p-2) ? 1.f : 0.f));
        if (p == 0 && c == 0) v = 0.f;
        if (p == 1 && c == 0) v = -1.f;
        g_Delta[idx] = v;
    }
}

__global__ void k_dtd() {
    int idx = blockIdx.x * blockDim.x + threadIdx.x;
    if (idx < Ldim*Ldim) {
        int i = idx >> 7, j = idx & 127;
        float s = 0.f;
        for (int p = 0; p < 128; p++) s += g_Delta[p*128 + i] * g_Delta[p*128 + j];
        g_DtD[idx] = s;
        float h = tf32_rna(s);
        g_DtDh[idx] = h;
        g_DtDl[idx] = tf32_rna(s - h);
    }
}

// ---------------- generic NT GEMM (precompute only, R4-proven) ----------------
__global__ void gemm_nt(const float* __restrict__ A, const float* __restrict__ B,
                        float* __restrict__ C, int n, int K) {
    __shared__ float As[32][33];
    __shared__ float Bs[32][33];
    int i0 = blockIdx.x * 32, j0 = blockIdx.y * 32;
    int tid = threadIdx.x;
    int tr = tid >> 5, tc = tid & 31;
    int ti = tid >> 4, tj = tid & 15;
    float a00=0.f, a01=0.f, a10=0.f, a11=0.f;
    for (int k0 = 0; k0 < K; k0 += 32) {
        #pragma unroll
        for (int r = 0; r < 4; r++) {
            As[tc][tr + 8*r] = A[(size_t)(i0 + tr + 8*r) * K + k0 + tc];
            Bs[tc][tr + 8*r] = B[(size_t)(j0 + tr + 8*r) * K + k0 + tc];
        }
        __syncthreads();
        #pragma unroll
        for (int kk = 0; kk < 32; kk++) {
            float av0 = As[kk][2*ti], av1 = As[kk][2*ti+1];
            float bv0 = Bs[kk][2*tj], bv1 = Bs[kk][2*tj+1];
            a00 += av0*bv0; a01 += av0*bv1; a10 += av1*bv0; a11 += av1*bv1;
        }
        __syncthreads();
    }
    int i = i0 + 2*ti, j = j0 + 2*tj;
    C[(size_t)i*n + j]     = a00; C[(size_t)i*n + j+1]     = a01;
    C[(size_t)(i+1)*n + j] = a10; C[(size_t)(i+1)*n + j+1] = a11;
}

// ---------------- trace / normalize / Rayleigh (precompute) ----------------
__global__ void k_trace(const float* __restrict__ m, int n) {
    __shared__ float sh[512];
    int t = threadIdx.x;
    sh[t] = (t < n) ? m[t*n + t] : 0.f;
    __syncthreads();
    for (int off = 256; off > 0; off >>= 1) {
        if (t < off) sh[t] += sh[t + off];
        __syncthreads();
    }
    if (t == 0) g_red[0] = sh[0];
}

__global__ void k_normmat(const float* __restrict__ src, float* __restrict__ dst, int nn) {
    float inv = 1.f / g_red[0];
    int idx = blockIdx.x * blockDim.x + threadIdx.x;
    if (idx < nn) dst[idx] = src[idx] * inv;
}

__global__ void k_rayleigh(const float* __restrict__ P, const float* __restrict__ S,
                           int n, int slot) {
    __shared__ float v[512];
    __shared__ float r1[512], r2[512];
    int t = threadIdx.x;
    float s = 0.f;
    for (int j = 0; j < n; j++) s += P[t*n + j] * (sinf(0.7331f * j + 0.1234f) + 1.5f);
    v[t] = s;
    __syncthreads();
    float w = 0.f;
    for (int j = 0; j < n; j++) w += S[t*n + j] * v[j];
    r1[t] = v[t] * w;
    r2[t] = v[t] * v[t];
    __syncthreads();
    for (int off = n >> 1; off > 0; off >>= 1) {
        if (t < off) { r1[t] += r1[t+off]; r2[t] += r2[t+off]; }
        __syncthreads();
    }
    if (t == 0) g_scal[slot] = r1[0] / r2[0];
}

__global__ void k_scalars() {
    float tau = 1.0f / (2.0f * (g_scal[0] + 0.1f * g_scal[1]));
    float lam2 = (tau * 0.1f > 0.1f) ? (0.1f / tau) : 0.1f;
    g_scal[2] = tau;
    g_scal[3] = tau * lam2;
}

// ---------------- tensor-core gradient: grid (4, 8, 5) ----------------
// z in 0..3: G[z] = U[:, z*512:(z+1)*512] @ x[:, same]^T   (B rows are n=j)
// z == 4   : G[4] = 0.1 * DtD @ A                           (B rows are k=p)
__global__ void __launch_bounds__(256) k_grad(int dummy) {
    if (g_done) return;
    __shared__ float As[2][2][32][18];
    __shared__ float Bs[2][2][64][18];
    int z = blockIdx.z;
    int i0 = blockIdx.x * 32, j0 = blockIdx.y * 64;
    int tid = threadIdx.x;
    int wid = tid >> 5, lane = tid & 31;
    int wm = wid >> 2, wn = wid & 3;
    int frow = 16*wm + (lane >> 2);
    int t2 = 2*(lane & 3);

    const float* Ah; const float* Al; int pA, kb0, nch;
    const float* Bh; const float* Bl; int pB; bool bnt;
    if (z < 4) {
        Ah = g_Uh; Al = g_Ul; pA = Mdim; kb0 = z*512; nch = 32;
        Bh = g_xh; Bl = g_xl; pB = Mdim; bnt = true;
    } else {
        Ah = g_DtDh; Al = g_DtDl; pA = Ldim; kb0 = 0; nch = 8;
        Bh = g_Ah; Bl = g_Al; pB = Ddim; bnt = false;
    }

    auto loadc = [&](int buf, int kb) {
        #pragma unroll
        for (int r = 0; r < 2; r++) {
            int e = tid + 256*r; int m = e >> 4, c = e & 15;
            int s = SLOT(c);
            As[buf][0][m][s] = Ah[(i0 + m)*pA + kb + c];
            As[buf][1][m][s] = Al[(i0 + m)*pA + kb + c];
        }
        if (bnt) {
            #pragma unroll
            for (int r = 0; r < 4; r++) {
                int e = tid + 256*r; int nn = e >> 4, c = e & 15;
                int s = SLOT(c);
                Bs[buf][0][nn][s] = Bh[(j0 + nn)*pB + kb + c];
                Bs[buf][1][nn][s] = Bl[(j0 + nn)*pB + kb + c];
            }
        } else {
            #pragma unroll
            for (int r = 0; r < 4; r++) {
                int e = tid + 256*r; int kk = e >> 6, nn = e & 63;
                int s = SLOT(kk);
                Bs[buf][0][nn][s] = Bh[(kb + kk)*pB + j0 + nn];
                Bs[buf][1][nn][s] = Bl[(kb + kk)*pB + j0 + nn];
            }
        }
    };

    float d[2][4] = {};
    loadc(0, kb0);
    __syncthreads();
    for (int ch = 0; ch < nch; ch++) {
        int b = ch & 1;
        if (ch + 1 < nch) loadc(b ^ 1, kb0 + 16*(ch + 1));
        #pragma unroll
        for (int g = 0; g < 2; g++) {
            int s = g*8 + t2;
            float2 ah0 = *(const float2*)&As[b][0][frow][s];
            float2 ah1 = *(const float2*)&As[b][0][frow + 8][s];
            float2 al0 = *(const float2*)&As[b][1][frow][s];
            float2 al1 = *(const float2*)&As[b][1][frow + 8][s];
            #pragma unroll
            for (int nt = 0; nt < 2; nt++) {
                int brow = 16*wn + 8*nt + (lane >> 2);
                float2 bh = *(const float2*)&Bs[b][0][brow][s];
                float2 bl = *(const float2*)&Bs[b][1][brow][s];
                mma8(d[nt], ah0, ah1, bh);
                mma8(d[nt], ah0, ah1, bl);
                mma8(d[nt], al0, al1, bh);
            }
        }
        __syncthreads();
    }
    float sc = (z == 4) ? 0.1f : 1.0f;
    float* outp = &g_G[z][0];
    #pragma unroll
    for (int nt = 0; nt < 2; nt++) {
        int cb = j0 + 16*wn + 8*nt + t2;
        int r0 = i0 + frow, r1 = r0 + 8;
        float2 v0 = make_float2(d[nt][0]*sc, d[nt][1]*sc);
        float2 v1 = make_float2(d[nt][2]*sc, d[nt][3]*sc);
        *(float2*)&outp[r0*Ddim + cb] = v0;
        *(float2*)&outp[r1*Ddim + cb] = v1;
    }
}

// ---------------- prox + momentum (R4) + A hi/lo split ----------------
__global__ void k_update(float coeff) {
    if (g_done) return;
    float tau = g_scal[2], thr = g_scal[3];
    int idx = blockIdx.x * blockDim.x + threadIdx.x;
    float g = g_G[0][idx] + g_G[1][idx] + g_G[2][idx] + g_G[3][idx] + g_G[4][idx];
    float aold = g_A[idx], b = g_Bm[idx];
    float zv = b - tau * g;
    float az = fabsf(zv) - thr;
    float anew = (az > 0.f) ? copysignf(az, zv) : 0.f;
    g_A[idx]  = anew;
    g_Bm[idx] = aold + coeff * (anew - aold);
    float h = tf32_rna(anew);
    g_Ah[idx] = h;
    g_Al[idx] = tf32_rna(anew - h);
}

// ---------------- tensor-core forward: T = A@x, U = mask*(T-py), U hi/lo ----------------
__global__ void __launch_bounds__(256) k_fwd(const float* __restrict__ py,
                                             const float* __restrict__ mask) {
    if (g_done) return;
    __shared__ float As[2][2][32][18];
    __shared__ float Bs[2][2][64][18];
    int i0 = blockIdx.x * 32, m0 = blockIdx.y * 64;
    int tid = threadIdx.x;
    int wid = tid >> 5, lane = tid & 31;
    int wm = wid >> 2, wn = wid & 3;
    int frow = 16*wm + (lane >> 2);
    int t2 = 2*(lane & 3);

    auto loadc = [&](int buf, int kb) {
        #pragma unroll
        for (int r = 0; r < 2; r++) {
            int e = tid + 256*r; int m = e >> 4, c = e & 15;
            int s = SLOT(c);
            As[buf][0][m][s] = g_Ah[(i0 + m)*Ddim + kb + c];
            As[buf][1][m][s] = g_Al[(i0 + m)*Ddim + kb + c];
        }
        #pragma unroll
        for (int r = 0; r < 4; r++) {
            int e = tid + 256*r; int kk = e >> 6, nn = e & 63;
            int s = SLOT(kk);
            Bs[buf][0][nn][s] = g_xh[(kb + kk)*Mdim + m0 + nn];
            Bs[buf][1][nn][s] = g_xl[(kb + kk)*Mdim + m0 + nn];
        }
    };

    float d[2][4] = {};
    loadc(0, 0);
    __syncthreads();
    for (int ch = 0; ch < 32; ch++) {
        int b = ch & 1;
        if (ch + 1 < 32) loadc(b ^ 1, 16*(ch + 1));
        #pragma unroll
        for (int g = 0; g < 2; g++) {
            int s = g*8 + t2;
            float2 ah0 = *(const float2*)&As[b][0][frow][s];
            float2 ah1 = *(const float2*)&As[b][0][frow + 8][s];
            float2 al0 = *(const float2*)&As[b][1][frow][s];
            float2 al1 = *(const float2*)&As[b][1][frow + 8][s];
            #pragma unroll
            for (int nt = 0; nt < 2; nt++) {
                int brow = 16*wn + 8*nt + (lane >> 2);
                float2 bh = *(const float2*)&Bs[b][0][brow][s];
                float2 bl = *(const float2*)&Bs[b][1][brow][s];
                mma8(d[nt], ah0, ah1, bh);
                mma8(d[nt], ah0, ah1, bl);
                mma8(d[nt], al0, al1, bh);
            }
        }
        __syncthreads();
    }
    #pragma unroll
    for (int nt = 0; nt < 2; nt++) {
        int cb = m0 + 16*wn + 8*nt + t2;
        int r0 = i0 + frow, r1 = r0 + 8;
        #pragma unroll
        for (int hr = 0; hr < 2; hr++) {
            int row = hr ? r1 : r0;
            float tv0 = d[nt][2*hr], tv1 = d[nt][2*hr + 1];
            size_t o = (size_t)row * Mdim + cb;
            float2 mk = *(const float2*)&mask[o];
            float2 pv = *(const float2*)&py[o];
            *(float2*)&g_T[o] = make_float2(tv0, tv1);
            float u0 = mk.x * (tv0 - pv.x);
            float u1 = mk.y * (tv1 - pv.y);
            float h0 = tf32_rna(u0), h1 = tf32_rna(u1);
            *(float2*)&g_Uh[o] = make_float2(h0, h1);
            *(float2*)&g_Ul[o] = make_float2(tf32_rna(u0 - h0), tf32_rna(u1 - h1));
        }
    }
}

// ---------------- convergence on Hankel tail (R4, 1024 threads) ----------------
__global__ void k_conv() {
    if (g_done) return;
    __shared__ float diag[128];
    __shared__ float r1[128], r2[128];
    int tid = threadIdx.x;           // 1024 threads
    int t = tid >> 3, s = tid & 7;
    float sum = 0.f;
    if (t < NTAIL) {
        for (int i = t + 1 + s; i < Ldim; i += 8)
            sum += g_T[i * Mdim + (Mdim + t - i)];
    }
    sum += __shfl_down_sync(0xffffffff, sum, 4, 8);
    sum += __shfl_down_sync(0xffffffff, sum, 2, 8);
    sum += __shfl_down_sync(0xffffffff, sum, 1, 8);
    if (s == 0 && t < 128) diag[t] = (t < NTAIL) ? sum / (float)(NTAIL - t) : 0.f;
    __syncthreads();
    if (tid < 128) {
        float a = (tid < NTAIL) ? diag[tid] : 0.f;
        float y = (tid < NTAIL) ? g_ytail[tid] : 0.f;
        float d = y - a;
        r1[tid] = d * d;
        r2[tid] = y * y;
    }
    __syncthreads();
    for (int off = 64; off > 0; off >>= 1) {
        if (tid < off) { r1[tid] += r1[tid + off]; r2[tid] += r2[tid + off]; }
        __syncthreads();
    }
    if (tid == 0 && sqrtf(r1[0] / r2[0]) <= 1e-5f) g_done = 1;
    if (tid < NTAIL) g_ytail[tid] = diag[tid];
}

// ---------------- output: (A@x, A) ----------------
__global__ void k_output(float* __restrict__ out, int out_size) {
    int idx = blockIdx.x * blockDim.x + threadIdx.x;
    if (idx >= out_size) return;
    if (idx < Ldim*Mdim) out[idx] = g_T[idx];
    else if (idx < Ldim*Mdim + Ldim*Ddim) out[idx] = g_A[idx - Ldim*Mdim];
}

extern "C" void kernel_launch(void* const* d_in, const int* in_sizes, int n_in,
                              void* d_out, int out_size) {
    const float* x    = (const float*)d_in[0];
    const float* py   = (const float*)d_in[1];
    const float* mask = (const float*)d_in[2];
    const float* y0   = (const float*)d_in[3];
    float* outp = (float*)d_out;

    void *pS, *pP0, *pP1, *pDtD, *pQ0, *pQ1;
    cudaGetSymbolAddress(&pS,   g_S);
    cudaGetSymbolAddress(&pP0,  g_P0);
    cudaGetSymbolAddress(&pP1,  g_P1);
    cudaGetSymbolAddress(&pDtD, g_DtD);
    cudaGetSymbolAddress(&pQ0,  g_Q0);
    cudaGetSymbolAddress(&pQ1,  g_Q1);

    k_init<<<(Ldim*Mdim + 255)/256, 256>>>(mask, py, y0);
    k_xsplit<<<(Ddim*Mdim + 255)/256, 256>>>(x);
    k_delta<<<(Ldim*Ldim + 255)/256, 256>>>();
    k_dtd<<<(Ldim*Ldim + 255)/256, 256>>>();

    // maxeig(x x^T): 10 trace-normalized squarings + Rayleigh
    gemm_nt<<<dim3(16,16), 256>>>(x, x, (float*)pS, Ddim, Mdim);
    k_trace<<<1, 512>>>((const float*)pS, Ddim);
    k_normmat<<<(Ddim*Ddim + 255)/256, 256>>>((const float*)pS, (float*)pP0, Ddim*Ddim);
    for (int i = 0; i < 10; i++) {
        gemm_nt<<<dim3(16,16), 256>>>((const float*)pP0, (const float*)pP0, (float*)pP1, Ddim, Ddim);
        k_trace<<<1, 512>>>((const float*)pP1, Ddim);
        k_normmat<<<(Ddim*Ddim + 255)/256, 256>>>((const float*)pP1, (float*)pP0, Ddim*Ddim);
    }
    k_rayleigh<<<1, Ddim>>>((const float*)pP0, (const float*)pS, Ddim, 0);

    // maxeig(DtD): 17 trace-normalized squarings + Rayleigh
    k_trace<<<1, 512>>>((const float*)pDtD, Ldim);
    k_normmat<<<(Ldim*Ldim + 255)/256, 256>>>((const float*)pDtD, (float*)pQ0, Ldim*Ldim);
    for (int i = 0; i < 17; i++) {
        gemm_nt<<<dim3(4,4), 256>>>((const float*)pQ0, (const float*)pQ0, (float*)pQ1, Ldim, Ldim);
        k_trace<<<1, 512>>>((const float*)pQ1, Ldim);
        k_normmat<<<(Ldim*Ldim + 255)/256, 256>>>((const float*)pQ1, (float*)pQ0, Ldim*Ldim);
    }
    k_rayleigh<<<1, Ldim>>>((const float*)pQ0, (const float*)pDtD, Ldim, 1);

    k_scalars<<<1, 1>>>();

    // FISTA loop: tensor-core GEMMs, 4 kernels/iter, device-side early exit
    float a = 1.0f;
    for (int it = 0; it < 200; it++) {
        float anew = (1.0f + sqrtf(1.0f + 4.0f * a * a)) * 0.5f;
        float coeff = (a - 1.0f) / anew;
        a = anew;
        k_grad<<<dim3(4, 8, 5), 256>>>(0);
        k_update<<<(Ldim*Ddim)/256, 256>>>(coeff);
        k_fwd<<<dim3(4, 32), 256>>>(py, mask);
        k_conv<<<1, 1024>>>();
    }

    k_output<<<(out_size + 255)/256, 256>>>(outp, out_size);
}

// round 9
// speedup vs baseline: 1.4529x; 1.4529x over previous
#include <cuda_runtime.h>
#include <math.h>

#define Ldim 128
#define Ddim 512
#define Mdim 2048
#define NTAIL 127

__device__ float g_A[Ldim*Ddim];
__device__ float g_Bm[Ldim*Ddim];
__device__ float g_T[Ldim*Mdim];
__device__ float g_U[Ldim*Mdim];
__device__ float g_G[5][Ldim*Ddim];
__device__ float g_S[Ddim*Ddim];
__device__ float g_P0[Ddim*Ddim];
__device__ float g_P1[Ddim*Ddim];
__device__ float g_Delta[Ldim*Ldim];
__device__ float g_DtD[Ldim*Ldim];
__device__ float g_Q0[Ldim*Ldim];
__device__ float g_Q1[Ldim*Ldim];
__device__ float g_ytail[NTAIL];
__device__ float g_red[4];
__device__ float g_scal[4];   // [0]=maxeig(xxT) [1]=maxeig(DtD) [2]=tau [3]=thr
__device__ int   g_done;

// ---------------- init / constants ----------------
__global__ void k_init(const float* __restrict__ mask, const float* __restrict__ py,
                       const float* __restrict__ y0) {
    int idx = blockIdx.x * blockDim.x + threadIdx.x;
    if (idx < Ldim*Ddim) { g_A[idx] = 0.f; g_Bm[idx] = 0.f; }
    if (idx < Ldim*Mdim) { g_U[idx] = -mask[idx] * py[idx]; }
    if (idx < NTAIL)     { g_ytail[idx] = y0[Mdim + idx]; }
    if (idx == 0)        { g_done = 0; }
}

__global__ void k_delta() {
    int idx = blockIdx.x * blockDim.x + threadIdx.x;
    if (idx < Ldim*Ldim) {
        int p = idx >> 7, c = idx & 127;
        float v = (c == p) ? 1.f : ((c == p-1) ? -2.f : ((c == p-2) ? 1.f : 0.f));
        if (p == 0 && c == 0) v = 0.f;
        if (p == 1 && c == 0) v = -1.f;
        g_Delta[idx] = v;
    }
}

__global__ void k_dtd() {
    int idx = blockIdx.x * blockDim.x + threadIdx.x;
    if (idx < Ldim*Ldim) {
        int i = idx >> 7, j = idx & 127;
        float s = 0.f;
        for (int p = 0; p < 128; p++) s += g_Delta[p*128 + i] * g_Delta[p*128 + j];
        g_DtD[idx] = s;
    }
}

// ---------------- fast NT self-GEMM (precompute): C = (A.A^T) * sc ----------------
// A row-major [n,K], C [n,n]. 32x64 tile, 256 threads, double-buffered + reg-prefetch
// (same proven body as the loop GEMMs). scaled!=0 -> sc = 1/trace(A)^2 from g_red[0].
__global__ void __launch_bounds__(256) gemm_sq(const float* __restrict__ A,
                                               float* __restrict__ C,
                                               int n, int K, int scaled) {
    __shared__ __align__(16) float Us[2][32][34];
    __shared__ __align__(16) float Xs[2][32][68];
    int i0 = blockIdx.x * 32, j0 = blockIdx.y * 64;
    int tid = threadIdx.x;
    int ti = tid >> 4, tj = tid & 15;
    int tr = tid >> 5, tc = tid & 31;
    float acc[2][4] = {};
    int nk = K >> 5;
    float ur[4], xr[8];

    auto load_regs = [&](int kt) {
        int k0 = kt * 32;
        #pragma unroll
        for (int r = 0; r < 4; r++)
            ur[r] = A[(size_t)(i0 + tr + 8*r) * K + k0 + tc];
        #pragma unroll
        for (int r = 0; r < 8; r++)
            xr[r] = A[(size_t)(j0 + tr + 8*r) * K + k0 + tc];
    };
    auto store_smem = [&](int b) {
        #pragma unroll
        for (int r = 0; r < 4; r++) Us[b][tc][tr + 8*r] = ur[r];
        #pragma unroll
        for (int r = 0; r < 8; r++) Xs[b][tc][tr + 8*r] = xr[r];
    };

    load_regs(0);
    store_smem(0);
    __syncthreads();
    for (int kt = 0; kt < nk; kt++) {
        int b = kt & 1;
        if (kt + 1 < nk) load_regs(kt + 1);
        float2 av = *(const float2*)&Us[b][0][2*ti];
        float4 bv = *(const float4*)&Xs[b][0][4*tj];
        #pragma unroll
        for (int kk = 0; kk < 32; kk++) {
            float2 av2; float4 bv2;
            if (kk < 31) {
                av2 = *(const float2*)&Us[b][kk+1][2*ti];
                bv2 = *(const float4*)&Xs[b][kk+1][4*tj];
            }
            acc[0][0] += av.x*bv.x; acc[0][1] += av.x*bv.y; acc[0][2] += av.x*bv.z; acc[0][3] += av.x*bv.w;
            acc[1][0] += av.y*bv.x; acc[1][1] += av.y*bv.y; acc[1][2] += av.y*bv.z; acc[1][3] += av.y*bv.w;
            if (kk < 31) { av = av2; bv = bv2; }
        }
        if (kt + 1 < nk) {
            store_smem((kt + 1) & 1);
            __syncthreads();
        }
    }
    float sc = 1.0f;
    if (scaled) { float t = g_red[0]; sc = 1.0f / (t * t); }
    int i = i0 + 2*ti, j = j0 + 4*tj;
    #pragma unroll
    for (int r = 0; r < 2; r++)
        #pragma unroll
        for (int c = 0; c < 4; c++)
            C[(size_t)(i + r) * n + j + c] = acc[r][c] * sc;
}

// ---------------- trace ----------------
__global__ void k_trace(const float* __restrict__ m, int n) {
    __shared__ float sh[512];
    int t = threadIdx.x;
    sh[t] = (t < n) ? m[t*n + t] : 0.f;
    __syncthreads();
    for (int off = 256; off > 0; off >>= 1) {
        if (t < off) sh[t] += sh[t + off];
        __syncthreads();
    }
    if (t == 0) g_red[0] = sh[0];
}

// ---------------- Rayleigh: v = P*r, lambda = (v^T S v)/(v^T v) ----------------
__global__ void k_rayleigh(const float* __restrict__ P, const float* __restrict__ S,
                           int n, int slot) {
    __shared__ float v[512];
    __shared__ float r1[512], r2[512];
    int t = threadIdx.x;
    float s = 0.f;
    for (int j = 0; j < n; j++) s += P[t*n + j] * (sinf(0.7331f * j + 0.1234f) + 1.5f);
    v[t] = s;
    __syncthreads();
    float w = 0.f;
    for (int j = 0; j < n; j++) w += S[t*n + j] * v[j];
    r1[t] = v[t] * w;
    r2[t] = v[t] * v[t];
    __syncthreads();
    for (int off = n >> 1; off > 0; off >>= 1) {
        if (t < off) { r1[t] += r1[t+off]; r2[t] += r2[t+off]; }
        __syncthreads();
    }
    if (t == 0) g_scal[slot] = r1[0] / r2[0];
}

__global__ void k_scalars() {
    float tau = 1.0f / (2.0f * (g_scal[0] + 0.1f * g_scal[1]));
    float lam2 = (tau * 0.1f > 0.1f) ? (0.1f / tau) : 0.1f;
    g_scal[2] = tau;
    g_scal[3] = tau * lam2;
}

// ---------------- gradient: z 0..3 -> U-chunk @ x^T (split-K), z==4 -> 0.1*DtD@A ----------------
// (R4-proven: double-buffered smem + register-prefetched inner loop)
__global__ void __launch_bounds__(256) gemm_grad(const float* __restrict__ x) {
    if (g_done) return;
    __shared__ __align__(16) float Us[2][32][34];
    __shared__ __align__(16) float Xs[2][32][68];
    int z = blockIdx.z;
    int i0 = blockIdx.x * 32, j0 = blockIdx.y * 64;
    int tid = threadIdx.x;
    int ti = tid >> 4, tj = tid & 15;
    int tr = tid >> 5, tc = tid & 31;
    int rr = tid >> 6, cc = tid & 63;
    float acc[2][4] = {};
    int nk = (z < 4) ? 16 : 4;
    float ur[4], xr[8];

    auto load_regs = [&](int kt) {
        if (z < 4) {
            int m0 = z * 512 + kt * 32;
            #pragma unroll
            for (int r = 0; r < 4; r++)
                ur[r] = g_U[(size_t)(i0 + tr + 8*r) * Mdim + m0 + tc];
            #pragma unroll
            for (int r = 0; r < 8; r++)
                xr[r] = x[(size_t)(j0 + tr + 8*r) * Mdim + m0 + tc];
        } else {
            int p0 = kt * 32;
            #pragma unroll
            for (int r = 0; r < 4; r++)
                ur[r] = g_DtD[(i0 + tr + 8*r) * Ldim + p0 + tc];
            #pragma unroll
            for (int r = 0; r < 8; r++)
                xr[r] = g_A[(p0 + rr + 4*r) * Ddim + j0 + cc];
        }
    };
    auto store_smem = [&](int b) {
        #pragma unroll
        for (int r = 0; r < 4; r++) Us[b][tc][tr + 8*r] = ur[r];
        if (z < 4) {
            #pragma unroll
            for (int r = 0; r < 8; r++) Xs[b][tc][tr + 8*r] = xr[r];
        } else {
            #pragma unroll
            for (int r = 0; r < 8; r++) Xs[b][rr + 4*r][cc] = xr[r];
        }
    };

    load_regs(0);
    store_smem(0);
    __syncthreads();
    for (int kt = 0; kt < nk; kt++) {
        int b = kt & 1;
        if (kt + 1 < nk) load_regs(kt + 1);
        float2 av = *(const float2*)&Us[b][0][2*ti];
        float4 bv = *(const float4*)&Xs[b][0][4*tj];
        #pragma unroll
        for (int kk = 0; kk < 32; kk++) {
            float2 av2; float4 bv2;
            if (kk < 31) {
                av2 = *(const float2*)&Us[b][kk+1][2*ti];
                bv2 = *(const float4*)&Xs[b][kk+1][4*tj];
            }
            acc[0][0] += av.x*bv.x; acc[0][1] += av.x*bv.y; acc[0][2] += av.x*bv.z; acc[0][3] += av.x*bv.w;
            acc[1][0] += av.y*bv.x; acc[1][1] += av.y*bv.y; acc[1][2] += av.y*bv.z; acc[1][3] += av.y*bv.w;
            if (kk < 31) { av = av2; bv = bv2; }
        }
        if (kt + 1 < nk) {
            store_smem((kt + 1) & 1);
            __syncthreads();
        }
    }
    float sc = (z == 4) ? 0.1f : 1.0f;
    int i = i0 + 2*ti, j = j0 + 4*tj;
    float* outp = &g_G[z][0];
    #pragma unroll
    for (int r = 0; r < 2; r++)
        #pragma unroll
        for (int c = 0; c < 4; c++)
            outp[(i + r) * Ddim + j + c] = acc[r][c] * sc;
}

// ---------------- prox + momentum ----------------
__global__ void k_update(float coeff) {
    if (g_done) return;
    float tau = g_scal[2], thr = g_scal[3];
    int idx = blockIdx.x * blockDim.x + threadIdx.x;
    float g = g_G[0][idx] + g_G[1][idx] + g_G[2][idx] + g_G[3][idx] + g_G[4][idx];
    float aold = g_A[idx], b = g_Bm[idx];
    float zv = b - tau * g;
    float az = fabsf(zv) - thr;
    float anew = (az > 0.f) ? copysignf(az, zv) : 0.f;
    g_A[idx]  = anew;
    g_Bm[idx] = aold + coeff * (anew - aold);
}

// ---------------- forward: T = A@x, U = mask*(T - py) ----------------
__global__ void __launch_bounds__(256) gemm_fwd(const float* __restrict__ x,
                                                const float* __restrict__ py,
                                                const float* __restrict__ mask) {
    if (g_done) return;
    __shared__ __align__(16) float As[2][32][34];
    __shared__ __align__(16) float Xs[2][32][68];
    int i0 = blockIdx.x * 32, m0 = blockIdx.y * 64;
    int tid = threadIdx.x;
    int ti = tid >> 4, tj = tid & 15;
    int tr = tid >> 5, tc = tid & 31;
    int rr = tid >> 6, cc = tid & 63;
    float acc[2][4] = {};
    float ar[4], xr[8];

    auto load_regs = [&](int kt) {
        int k0 = kt * 32;
        #pragma unroll
        for (int r = 0; r < 4; r++)
            ar[r] = g_A[(i0 + tr + 8*r) * Ddim + k0 + tc];
        #pragma unroll
        for (int r = 0; r < 8; r++)
            xr[r] = x[(size_t)(k0 + rr + 4*r) * Mdim + m0 + cc];
    };
    auto store_smem = [&](int b) {
        #pragma unroll
        for (int r = 0; r < 4; r++) As[b][tc][tr + 8*r] = ar[r];
        #pragma unroll
        for (int r = 0; r < 8; r++) Xs[b][rr + 4*r][cc] = xr[r];
    };

    load_regs(0);
    store_smem(0);
    __syncthreads();
    for (int kt = 0; kt < 16; kt++) {
        int b = kt & 1;
        if (kt + 1 < 16) load_regs(kt + 1);
        float2 av = *(const float2*)&As[b][0][2*ti];
        float4 bv = *(const float4*)&Xs[b][0][4*tj];
        #pragma unroll
        for (int kk = 0; kk < 32; kk++) {
            float2 av2; float4 bv2;
            if (kk < 31) {
                av2 = *(const float2*)&As[b][kk+1][2*ti];
                bv2 = *(const float4*)&Xs[b][kk+1][4*tj];
            }
            acc[0][0] += av.x*bv.x; acc[0][1] += av.x*bv.y; acc[0][2] += av.x*bv.z; acc[0][3] += av.x*bv.w;
            acc[1][0] += av.y*bv.x; acc[1][1] += av.y*bv.y; acc[1][2] += av.y*bv.z; acc[1][3] += av.y*bv.w;
            if (kk < 31) { av = av2; bv = bv2; }
        }
        if (kt + 1 < 16) {
            store_smem((kt + 1) & 1);
            __syncthreads();
        }
    }
    #pragma unroll
    for (int r = 0; r < 2; r++) {
        int i = i0 + 2*ti + r;
        #pragma unroll
        for (int c = 0; c < 4; c++) {
            int m = m0 + 4*tj + c;
            size_t o = (size_t)i * Mdim + m;
            float t = acc[r][c];
            g_T[o] = t;
            g_U[o] = mask[o] * (t - py[o]);
        }
    }
}

// ---------------- convergence on Hankel tail (1024 threads, 8-way per diagonal) ----------------
__global__ void k_conv() {
    if (g_done) return;
    __shared__ float diag[128];
    __shared__ float r1[128], r2[128];
    int tid = threadIdx.x;           // 1024 threads
    int t = tid >> 3, s = tid & 7;   // t: diagonal 0..127, s: chunk 0..7
    float sum = 0.f;
    if (t < NTAIL) {
        for (int i = t + 1 + s; i < Ldim; i += 8)
            sum += g_T[i * Mdim + (Mdim + t - i)];
    }
    sum += __shfl_down_sync(0xffffffff, sum, 4, 8);
    sum += __shfl_down_sync(0xffffffff, sum, 2, 8);
    sum += __shfl_down_sync(0xffffffff, sum, 1, 8);
    if (s == 0 && t < 128) diag[t] = (t < NTAIL) ? sum / (float)(NTAIL - t) : 0.f;
    __syncthreads();
    if (tid < 128) {
        float a = (tid < NTAIL) ? diag[tid] : 0.f;
        float y = (tid < NTAIL) ? g_ytail[tid] : 0.f;
        float d = y - a;
        r1[tid] = d * d;
        r2[tid] = y * y;
    }
    __syncthreads();
    for (int off = 64; off > 0; off >>= 1) {
        if (tid < off) { r1[tid] += r1[tid + off]; r2[tid] += r2[tid + off]; }
        __syncthreads();
    }
    if (tid == 0 && sqrtf(r1[0] / r2[0]) <= 1e-5f) g_done = 1;
    if (tid < NTAIL) g_ytail[tid] = diag[tid];
}

// ---------------- output: (A@x, A) ----------------
__global__ void k_output(float* __restrict__ out, int out_size) {
    int idx = blockIdx.x * blockDim.x + threadIdx.x;
    if (idx >= out_size) return;
    if (idx < Ldim*Mdim) out[idx] = g_T[idx];
    else if (idx < Ldim*Mdim + Ldim*Ddim) out[idx] = g_A[idx - Ldim*Mdim];
}

extern "C" void kernel_launch(void* const* d_in, const int* in_sizes, int n_in,
                              void* d_out, int out_size) {
    const float* x    = (const float*)d_in[0];
    const float* py   = (const float*)d_in[1];
    const float* mask = (const float*)d_in[2];
    const float* y0   = (const float*)d_in[3];
    float* outp = (float*)d_out;

    void *pS, *pP0, *pP1, *pDtD, *pQ0, *pQ1;
    cudaGetSymbolAddress(&pS,   g_S);
    cudaGetSymbolAddress(&pP0,  g_P0);
    cudaGetSymbolAddress(&pP1,  g_P1);
    cudaGetSymbolAddress(&pDtD, g_DtD);
    cudaGetSymbolAddress(&pQ0,  g_Q0);
    cudaGetSymbolAddress(&pQ1,  g_Q1);

    k_init<<<(Ldim*Mdim + 255)/256, 256>>>(mask, py, y0);
    k_delta<<<(Ldim*Ldim + 255)/256, 256>>>();
    k_dtd<<<(Ldim*Ldim + 255)/256, 256>>>();

    // maxeig(x x^T): S = x x^T, then 10 trace-normalized squarings + Rayleigh.
    // Normalization folded into the squaring GEMM: P_{i+1} = P_i^2 / tr(P_i)^2.
    gemm_sq<<<dim3(16, 8), 256>>>(x, (float*)pS, Ddim, Mdim, 0);
    k_trace<<<1, 512>>>((const float*)pS, Ddim);
    {
        float* bufs[2] = { (float*)pP0, (float*)pP1 };
        const float* cur = (const float*)pS;
        for (int i = 0; i < 10; i++) {
            float* nxt = bufs[i & 1];
            gemm_sq<<<dim3(16, 8), 256>>>(cur, nxt, Ddim, Ddim, 1);
            k_trace<<<1, 512>>>(nxt, Ddim);
            cur = nxt;
        }
        k_rayleigh<<<1, Ddim>>>(cur, (const float*)pS, Ddim, 0);
    }

    // maxeig(DtD): 17 trace-normalized squarings + Rayleigh (normalization folded)
    k_trace<<<1, 512>>>((const float*)pDtD, Ldim);
    {
        float* bufs[2] = { (float*)pQ0, (float*)pQ1 };
        const float* cur = (const float*)pDtD;
        for (int i = 0; i < 17; i++) {
            float* nxt = bufs[i & 1];
            gemm_sq<<<dim3(4, 2), 256>>>(cur, nxt, Ldim, Ldim, 1);
            k_trace<<<1, 512>>>(nxt, Ldim);
            cur = nxt;
        }
        k_rayleigh<<<1, Ldim>>>(cur, (const float*)pDtD, Ldim, 1);
    }

    k_scalars<<<1, 1>>>();

    // FISTA loop: R4-proven 4 kernels per iteration, device-side early exit
    float a = 1.0f;
    for (int it = 0; it < 200; it++) {
        float anew = (1.0f + sqrtf(1.0f + 4.0f * a * a)) * 0.5f;
        float coeff = (a - 1.0f) / anew;
        a = anew;
        gemm_grad<<<dim3(Ldim/32, Ddim/64, 5), 256>>>(x);
        k_update<<<(Ldim*Ddim)/256, 256>>>(coeff);
        gemm_fwd<<<dim3(Ldim/32, Mdim/64), 256>>>(x, py, mask);
        k_conv<<<1, 1024>>>();
    }

    k_output<<<(out_size + 255)/256, 256>>>(outp, out_size);
}

// round 10
// speedup vs baseline: 1.6312x; 1.1227x over previous
#include <cuda_runtime.h>
#include <math.h>

#define Ldim 128
#define Ddim 512
#define Mdim 2048
#define NTAIL 127

__device__ float g_A[Ldim*Ddim];
__device__ float g_Bm[Ldim*Ddim];
__device__ float g_T[Ldim*Mdim];
__device__ float g_U[Ldim*Mdim];
__device__ float g_G[5][Ldim*Ddim];
__device__ float g_S[Ddim*Ddim];
__device__ float g_P0[Ddim*Ddim];
__device__ float g_P1[Ddim*Ddim];
__device__ float g_Delta[Ldim*Ldim];
__device__ float g_DtD[Ldim*Ldim];
__device__ float g_Q0[Ldim*Ldim];
__device__ float g_Q1[Ldim*Ldim];
__device__ float g_ytail[NTAIL];
__device__ float g_red[4];
__device__ float g_scal[4];   // [0]=maxeig(xxT) [1]=maxeig(DtD) [2]=tau [3]=thr
__device__ int   g_done;

// ---------------- init / constants ----------------
__global__ void k_init(const float* __restrict__ mask, const float* __restrict__ py,
                       const float* __restrict__ y0) {
    int idx = blockIdx.x * blockDim.x + threadIdx.x;
    if (idx < Ldim*Ddim) { g_A[idx] = 0.f; g_Bm[idx] = 0.f; }
    if (idx < Ldim*Mdim) { g_U[idx] = -mask[idx] * py[idx]; }
    if (idx < NTAIL)     { g_ytail[idx] = y0[Mdim + idx]; }
    if (idx == 0)        { g_done = 0; }
}

__global__ void k_delta() {
    int idx = blockIdx.x * blockDim.x + threadIdx.x;
    if (idx < Ldim*Ldim) {
        int p = idx >> 7, c = idx & 127;
        float v = (c == p) ? 1.f : ((c == p-1) ? -2.f : ((c == p-2) ? 1.f : 0.f));
        if (p == 0 && c == 0) v = 0.f;
        if (p == 1 && c == 0) v = -1.f;
        g_Delta[idx] = v;
    }
}

__global__ void k_dtd() {
    int idx = blockIdx.x * blockDim.x + threadIdx.x;
    if (idx < Ldim*Ldim) {
        int i = idx >> 7, j = idx & 127;
        float s = 0.f;
        for (int p = 0; p < 128; p++) s += g_Delta[p*128 + i] * g_Delta[p*128 + j];
        g_DtD[idx] = s;
    }
}

// ---------------- fast NT self-GEMM (precompute): C = (A.A^T) * sc ----------------
__global__ void __launch_bounds__(256) gemm_sq(const float* __restrict__ A,
                                               float* __restrict__ C,
                                               int n, int K, int scaled) {
    __shared__ __align__(16) float Us[2][32][34];
    __shared__ __align__(16) float Xs[2][32][68];
    int i0 = blockIdx.x * 32, j0 = blockIdx.y * 64;
    int tid = threadIdx.x;
    int ti = tid >> 4, tj = tid & 15;
    int tr = tid >> 5, tc = tid & 31;
    float acc[2][4] = {};
    int nk = K >> 5;
    float ur[4], xr[8];

    auto load_regs = [&](int kt) {
        int k0 = kt * 32;
        #pragma unroll
        for (int r = 0; r < 4; r++)
            ur[r] = A[(size_t)(i0 + tr + 8*r) * K + k0 + tc];
        #pragma unroll
        for (int r = 0; r < 8; r++)
            xr[r] = A[(size_t)(j0 + tr + 8*r) * K + k0 + tc];
    };
    auto store_smem = [&](int b) {
        #pragma unroll
        for (int r = 0; r < 4; r++) Us[b][tc][tr + 8*r] = ur[r];
        #pragma unroll
        for (int r = 0; r < 8; r++) Xs[b][tc][tr + 8*r] = xr[r];
    };

    load_regs(0);
    store_smem(0);
    __syncthreads();
    for (int kt = 0; kt < nk; kt++) {
        int b = kt & 1;
        if (kt + 1 < nk) load_regs(kt + 1);
        float2 av = *(const float2*)&Us[b][0][2*ti];
        float4 bv = *(const float4*)&Xs[b][0][4*tj];
        #pragma unroll
        for (int kk = 0; kk < 32; kk++) {
            float2 av2; float4 bv2;
            if (kk < 31) {
                av2 = *(const float2*)&Us[b][kk+1][2*ti];
                bv2 = *(const float4*)&Xs[b][kk+1][4*tj];
            }
            acc[0][0] += av.x*bv.x; acc[0][1] += av.x*bv.y; acc[0][2] += av.x*bv.z; acc[0][3] += av.x*bv.w;
            acc[1][0] += av.y*bv.x; acc[1][1] += av.y*bv.y; acc[1][2] += av.y*bv.z; acc[1][3] += av.y*bv.w;
            if (kk < 31) { av = av2; bv = bv2; }
        }
        if (kt + 1 < nk) {
            store_smem((kt + 1) & 1);
            __syncthreads();
        }
    }
    float sc = 1.0f;
    if (scaled) { float t = g_red[0]; sc = 1.0f / (t * t); }
    int i = i0 + 2*ti, j = j0 + 4*tj;
    #pragma unroll
    for (int r = 0; r < 2; r++)
        #pragma unroll
        for (int c = 0; c < 4; c++)
            C[(size_t)(i + r) * n + j + c] = acc[r][c] * sc;
}

// ---------------- trace ----------------
__global__ void k_trace(const float* __restrict__ m, int n) {
    __shared__ float sh[512];
    int t = threadIdx.x;
    sh[t] = (t < n) ? m[t*n + t] : 0.f;
    __syncthreads();
    for (int off = 256; off > 0; off >>= 1) {
        if (t < off) sh[t] += sh[t + off];
        __syncthreads();
    }
    if (t == 0) g_red[0] = sh[0];
}

// ---------------- Rayleigh: v = P*r, lambda = (v^T S v)/(v^T v) ----------------
__global__ void k_rayleigh(const float* __restrict__ P, const float* __restrict__ S,
                           int n, int slot) {
    __shared__ float v[512];
    __shared__ float r1[512], r2[512];
    int t = threadIdx.x;
    float s = 0.f;
    for (int j = 0; j < n; j++) s += P[t*n + j] * (sinf(0.7331f * j + 0.1234f) + 1.5f);
    v[t] = s;
    __syncthreads();
    float w = 0.f;
    for (int j = 0; j < n; j++) w += S[t*n + j] * v[j];
    r1[t] = v[t] * w;
    r2[t] = v[t] * v[t];
    __syncthreads();
    for (int off = n >> 1; off > 0; off >>= 1) {
        if (t < off) { r1[t] += r1[t+off]; r2[t] += r2[t+off]; }
        __syncthreads();
    }
    if (t == 0) g_scal[slot] = r1[0] / r2[0];
}

__global__ void k_scalars() {
    float tau = 1.0f / (2.0f * (g_scal[0] + 0.1f * g_scal[1]));
    float lam2 = (tau * 0.1f > 0.1f) ? (0.1f / tau) : 0.1f;
    g_scal[2] = tau;
    g_scal[3] = tau * lam2;
}

// ---------------- gradient + (z==5) convergence check ----------------
// z 0..3 -> U-chunk @ x^T (split-K), z==4 -> 0.1*DtD@A,
// z==5 (block x==0,y==0 only) -> Hankel-tail convergence of PREVIOUS iteration's T.
__global__ void __launch_bounds__(256) gemm_grad(const float* __restrict__ x, int it) {
    if (g_done) return;
    int z = blockIdx.z;
    int tid = threadIdx.x;

    if (z == 5) {
        if (blockIdx.x != 0 || blockIdx.y != 0) return;
        if (it == 0) return;   // no T yet
        __shared__ float diag[128], r1[128], r2[128];
        int t = tid >> 1, s = tid & 1;   // 2 threads per diagonal
        float sum = 0.f;
        if (t < NTAIL) {
            for (int i = t + 1 + s; i < Ldim; i += 2)
                sum += g_T[i * Mdim + (Mdim + t - i)];
        }
        sum += __shfl_down_sync(0xffffffff, sum, 1, 2);
        if (s == 0 && t < 128) diag[t] = (t < NTAIL) ? sum / (float)(NTAIL - t) : 0.f;
        __syncthreads();
        if (tid < 128) {
            float a = (tid < NTAIL) ? diag[tid] : 0.f;
            float y = (tid < NTAIL) ? g_ytail[tid] : 0.f;
            float d = y - a;
            r1[tid] = d * d;
            r2[tid] = y * y;
        }
        __syncthreads();
        for (int off = 64; off > 0; off >>= 1) {
            if (tid < off) { r1[tid] += r1[tid + off]; r2[tid] += r2[tid + off]; }
            __syncthreads();
        }
        if (tid == 0 && sqrtf(r1[0] / r2[0]) <= 1e-5f) g_done = 1;
        if (tid < NTAIL) g_ytail[tid] = diag[tid];
        return;
    }

    __shared__ __align__(16) float Us[2][32][34];
    __shared__ __align__(16) float Xs[2][32][68];
    int i0 = blockIdx.x * 32, j0 = blockIdx.y * 64;
    int ti = tid >> 4, tj = tid & 15;
    int tr = tid >> 5, tc = tid & 31;
    int rr = tid >> 6, cc = tid & 63;
    float acc[2][4] = {};
    int nk = (z < 4) ? 16 : 4;
    float ur[4], xr[8];

    auto load_regs = [&](int kt) {
        if (z < 4) {
            int m0 = z * 512 + kt * 32;
            #pragma unroll
            for (int r = 0; r < 4; r++)
                ur[r] = g_U[(size_t)(i0 + tr + 8*r) * Mdim + m0 + tc];
            #pragma unroll
            for (int r = 0; r < 8; r++)
                xr[r] = x[(size_t)(j0 + tr + 8*r) * Mdim + m0 + tc];
        } else {
            int p0 = kt * 32;
            #pragma unroll
            for (int r = 0; r < 4; r++)
                ur[r] = g_DtD[(i0 + tr + 8*r) * Ldim + p0 + tc];
            #pragma unroll
            for (int r = 0; r < 8; r++)
                xr[r] = g_A[(p0 + rr + 4*r) * Ddim + j0 + cc];
        }
    };
    auto store_smem = [&](int b) {
        #pragma unroll
        for (int r = 0; r < 4; r++) Us[b][tc][tr + 8*r] = ur[r];
        if (z < 4) {
            #pragma unroll
            for (int r = 0; r < 8; r++) Xs[b][tc][tr + 8*r] = xr[r];
        } else {
            #pragma unroll
            for (int r = 0; r < 8; r++) Xs[b][rr + 4*r][cc] = xr[r];
        }
    };

    load_regs(0);
    store_smem(0);
    __syncthreads();
    for (int kt = 0; kt < nk; kt++) {
        int b = kt & 1;
        if (kt + 1 < nk) load_regs(kt + 1);
        float2 av = *(const float2*)&Us[b][0][2*ti];
        float4 bv = *(const float4*)&Xs[b][0][4*tj];
        #pragma unroll
        for (int kk = 0; kk < 32; kk++) {
            float2 av2; float4 bv2;
            if (kk < 31) {
                av2 = *(const float2*)&Us[b][kk+1][2*ti];
                bv2 = *(const float4*)&Xs[b][kk+1][4*tj];
            }
            acc[0][0] += av.x*bv.x; acc[0][1] += av.x*bv.y; acc[0][2] += av.x*bv.z; acc[0][3] += av.x*bv.w;
            acc[1][0] += av.y*bv.x; acc[1][1] += av.y*bv.y; acc[1][2] += av.y*bv.z; acc[1][3] += av.y*bv.w;
            if (kk < 31) { av = av2; bv = bv2; }
        }
        if (kt + 1 < nk) {
            store_smem((kt + 1) & 1);
            __syncthreads();
        }
    }
    float sc = (z == 4) ? 0.1f : 1.0f;
    int i = i0 + 2*ti, j = j0 + 4*tj;
    float* outp = &g_G[z][0];
    #pragma unroll
    for (int r = 0; r < 2; r++)
        #pragma unroll
        for (int c = 0; c < 4; c++)
            outp[(i + r) * Ddim + j + c] = acc[r][c] * sc;
}

// ---------------- prox + momentum ----------------
__global__ void k_update(float coeff) {
    if (g_done) return;
    float tau = g_scal[2], thr = g_scal[3];
    int idx = blockIdx.x * blockDim.x + threadIdx.x;
    float g = g_G[0][idx] + g_G[1][idx] + g_G[2][idx] + g_G[3][idx] + g_G[4][idx];
    float aold = g_A[idx], b = g_Bm[idx];
    float zv = b - tau * g;
    float az = fabsf(zv) - thr;
    float anew = (az > 0.f) ? copysignf(az, zv) : 0.f;
    g_A[idx]  = anew;
    g_Bm[idx] = aold + coeff * (anew - aold);
}

// ---------------- forward: T = A@x, U = mask*(T - py) ----------------
__global__ void __launch_bounds__(256) gemm_fwd(const float* __restrict__ x,
                                                const float* __restrict__ py,
                                                const float* __restrict__ mask) {
    if (g_done) return;
    __shared__ __align__(16) float As[2][32][34];
    __shared__ __align__(16) float Xs[2][32][68];
    int i0 = blockIdx.x * 32, m0 = blockIdx.y * 64;
    int tid = threadIdx.x;
    int ti = tid >> 4, tj = tid & 15;
    int tr = tid >> 5, tc = tid & 31;
    int rr = tid >> 6, cc = tid & 63;
    float acc[2][4] = {};
    float ar[4], xr[8];

    auto load_regs = [&](int kt) {
        int k0 = kt * 32;
        #pragma unroll
        for (int r = 0; r < 4; r++)
            ar[r] = g_A[(i0 + tr + 8*r) * Ddim + k0 + tc];
        #pragma unroll
        for (int r = 0; r < 8; r++)
            xr[r] = x[(size_t)(k0 + rr + 4*r) * Mdim + m0 + cc];
    };
    auto store_smem = [&](int b) {
        #pragma unroll
        for (int r = 0; r < 4; r++) As[b][tc][tr + 8*r] = ar[r];
        #pragma unroll
        for (int r = 0; r < 8; r++) Xs[b][rr + 4*r][cc] = xr[r];
    };

    load_regs(0);
    store_smem(0);
    __syncthreads();
    for (int kt = 0; kt < 16; kt++) {
        int b = kt & 1;
        if (kt + 1 < 16) load_regs(kt + 1);
        float2 av = *(const float2*)&As[b][0][2*ti];
        float4 bv = *(const float4*)&Xs[b][0][4*tj];
        #pragma unroll
        for (int kk = 0; kk < 32; kk++) {
            float2 av2; float4 bv2;
            if (kk < 31) {
                av2 = *(const float2*)&As[b][kk+1][2*ti];
                bv2 = *(const float4*)&Xs[b][kk+1][4*tj];
            }
            acc[0][0] += av.x*bv.x; acc[0][1] += av.x*bv.y; acc[0][2] += av.x*bv.z; acc[0][3] += av.x*bv.w;
            acc[1][0] += av.y*bv.x; acc[1][1] += av.y*bv.y; acc[1][2] += av.y*bv.z; acc[1][3] += av.y*bv.w;
            if (kk < 31) { av = av2; bv = bv2; }
        }
        if (kt + 1 < 16) {
            store_smem((kt + 1) & 1);
            __syncthreads();
        }
    }
    #pragma unroll
    for (int r = 0; r < 2; r++) {
        int i = i0 + 2*ti + r;
        #pragma unroll
        for (int c = 0; c < 4; c++) {
            int m = m0 + 4*tj + c;
            size_t o = (size_t)i * Mdim + m;
            float t = acc[r][c];
            g_T[o] = t;
            g_U[o] = mask[o] * (t - py[o]);
        }
    }
}

// ---------------- output: (A@x, A) ----------------
__global__ void k_output(float* __restrict__ out, int out_size) {
    int idx = blockIdx.x * blockDim.x + threadIdx.x;
    if (idx >= out_size) return;
    if (idx < Ldim*Mdim) out[idx] = g_T[idx];
    else if (idx < Ldim*Mdim + Ldim*Ddim) out[idx] = g_A[idx - Ldim*Mdim];
}

extern "C" void kernel_launch(void* const* d_in, const int* in_sizes, int n_in,
                              void* d_out, int out_size) {
    const float* x    = (const float*)d_in[0];
    const float* py   = (const float*)d_in[1];
    const float* mask = (const float*)d_in[2];
    const float* y0   = (const float*)d_in[3];
    float* outp = (float*)d_out;

    void *pS, *pP0, *pP1, *pDtD, *pQ0, *pQ1;
    cudaGetSymbolAddress(&pS,   g_S);
    cudaGetSymbolAddress(&pP0,  g_P0);
    cudaGetSymbolAddress(&pP1,  g_P1);
    cudaGetSymbolAddress(&pDtD, g_DtD);
    cudaGetSymbolAddress(&pQ0,  g_Q0);
    cudaGetSymbolAddress(&pQ1,  g_Q1);

    k_init<<<(Ldim*Mdim + 255)/256, 256>>>(mask, py, y0);
    k_delta<<<(Ldim*Ldim + 255)/256, 256>>>();
    k_dtd<<<(Ldim*Ldim + 255)/256, 256>>>();

    // maxeig(x x^T): S = x x^T, then 10 trace-normalized squarings + Rayleigh
    gemm_sq<<<dim3(16, 8), 256>>>(x, (float*)pS, Ddim, Mdim, 0);
    k_trace<<<1, 512>>>((const float*)pS, Ddim);
    {
        float* bufs[2] = { (float*)pP0, (float*)pP1 };
        const float* cur = (const float*)pS;
        for (int i = 0; i < 10; i++) {
            float* nxt = bufs[i & 1];
            gemm_sq<<<dim3(16, 8), 256>>>(cur, nxt, Ddim, Ddim, 1);
            k_trace<<<1, 512>>>(nxt, Ddim);
            cur = nxt;
        }
        k_rayleigh<<<1, Ddim>>>(cur, (const float*)pS, Ddim, 0);
    }

    // maxeig(DtD): top eigen-cluster of DtD is within ~0.5% of 16 and its term
    // contributes only ~0.03% to tau -> 4 squarings suffice.
    k_trace<<<1, 512>>>((const float*)pDtD, Ldim);
    {
        float* bufs[2] = { (float*)pQ0, (float*)pQ1 };
        const float* cur = (const float*)pDtD;
        for (int i = 0; i < 4; i++) {
            float* nxt = bufs[i & 1];
            gemm_sq<<<dim3(4, 2), 256>>>(cur, nxt, Ldim, Ldim, 1);
            k_trace<<<1, 512>>>(nxt, Ldim);
            cur = nxt;
        }
        k_rayleigh<<<1, Ldim>>>(cur, (const float*)pDtD, Ldim, 1);
    }

    k_scalars<<<1, 1>>>();

    // FISTA loop: 3 kernels/iter (conv folded into grad's z==5 slice)
    float a = 1.0f;
    for (int it = 0; it < 200; it++) {
        float anew = (1.0f + sqrtf(1.0f + 4.0f * a * a)) * 0.5f;
        float coeff = (a - 1.0f) / anew;
        a = anew;
        gemm_grad<<<dim3(Ldim/32, Ddim/64, 6), 256>>>(x, it);
        k_update<<<(Ldim*Ddim)/256, 256>>>(coeff);
        gemm_fwd<<<dim3(Ldim/32, Mdim/64), 256>>>(x, py, mask);
    }

    k_output<<<(out_size + 255)/256, 256>>>(outp, out_size);
}

// round 11
// speedup vs baseline: 1.9574x; 1.1999x over previous
#include <cuda_runtime.h>
#include <math.h>

#define Ldim 128
#define Ddim 512
#define Mdim 2048
#define NTAIL 127
#define NG 9

__device__ float g_A[Ldim*Ddim];
__device__ float g_Bm[Ldim*Ddim];
__device__ float g_T[Ldim*Mdim];
__device__ float g_U[Ldim*Mdim];
__device__ float g_G[NG][Ldim*Ddim];
__device__ float g_S[Ddim*Ddim];
__device__ float g_P0[Ddim*Ddim];
__device__ float g_P1[Ddim*Ddim];
__device__ float g_Delta[Ldim*Ldim];
__device__ float g_DtD[Ldim*Ldim];
__device__ float g_Q0[Ldim*Ldim];
__device__ float g_Q1[Ldim*Ldim];
__device__ float g_ytail[NTAIL];
__device__ float g_red[4];
__device__ float g_scal[4];   // [0]=maxeig(xxT) [1]=maxeig(DtD) [2]=tau [3]=thr
__device__ int   g_done;

// ---------------- init / constants ----------------
__global__ void k_init(const float* __restrict__ mask, const float* __restrict__ py,
                       const float* __restrict__ y0) {
    int idx = blockIdx.x * blockDim.x + threadIdx.x;
    if (idx < Ldim*Ddim) { g_A[idx] = 0.f; g_Bm[idx] = 0.f; }
    if (idx < Ldim*Mdim) { g_U[idx] = -mask[idx] * py[idx]; }
    if (idx < NTAIL)     { g_ytail[idx] = y0[Mdim + idx]; }
    if (idx == 0)        { g_done = 0; }
}

__global__ void k_delta() {
    int idx = blockIdx.x * blockDim.x + threadIdx.x;
    if (idx < Ldim*Ldim) {
        int p = idx >> 7, c = idx & 127;
        float v = (c == p) ? 1.f : ((c == p-1) ? -2.f : ((c == p-2) ? 1.f : 0.f));
        if (p == 0 && c == 0) v = 0.f;
        if (p == 1 && c == 0) v = -1.f;
        g_Delta[idx] = v;
    }
}

__global__ void k_dtd() {
    int idx = blockIdx.x * blockDim.x + threadIdx.x;
    if (idx < Ldim*Ldim) {
        int i = idx >> 7, j = idx & 127;
        float s = 0.f;
        for (int p = 0; p < 128; p++) s += g_Delta[p*128 + i] * g_Delta[p*128 + j];
        g_DtD[idx] = s;
    }
}

// ---------------- fast NT self-GEMM (precompute): C = (A.A^T) * sc ----------------
__global__ void __launch_bounds__(256) gemm_sq(const float* __restrict__ A,
                                               float* __restrict__ C,
                                               int n, int K, int scaled) {
    __shared__ __align__(16) float Us[2][32][34];
    __shared__ __align__(16) float Xs[2][32][68];
    int i0 = blockIdx.x * 32, j0 = blockIdx.y * 64;
    int tid = threadIdx.x;
    int ti = tid >> 4, tj = tid & 15;
    int tr = tid >> 5, tc = tid & 31;
    float acc[2][4] = {};
    int nk = K >> 5;
    float ur[4], xr[8];

    auto load_regs = [&](int kt) {
        int k0 = kt * 32;
        #pragma unroll
        for (int r = 0; r < 4; r++)
            ur[r] = A[(size_t)(i0 + tr + 8*r) * K + k0 + tc];
        #pragma unroll
        for (int r = 0; r < 8; r++)
            xr[r] = A[(size_t)(j0 + tr + 8*r) * K + k0 + tc];
    };
    auto store_smem = [&](int b) {
        #pragma unroll
        for (int r = 0; r < 4; r++) Us[b][tc][tr + 8*r] = ur[r];
        #pragma unroll
        for (int r = 0; r < 8; r++) Xs[b][tc][tr + 8*r] = xr[r];
    };

    load_regs(0);
    store_smem(0);
    __syncthreads();
    for (int kt = 0; kt < nk; kt++) {
        int b = kt & 1;
        if (kt + 1 < nk) load_regs(kt + 1);
        float2 av = *(const float2*)&Us[b][0][2*ti];
        float4 bv = *(const float4*)&Xs[b][0][4*tj];
        #pragma unroll
        for (int kk = 0; kk < 32; kk++) {
            float2 av2; float4 bv2;
            if (kk < 31) {
                av2 = *(const float2*)&Us[b][kk+1][2*ti];
                bv2 = *(const float4*)&Xs[b][kk+1][4*tj];
            }
            acc[0][0] += av.x*bv.x; acc[0][1] += av.x*bv.y; acc[0][2] += av.x*bv.z; acc[0][3] += av.x*bv.w;
            acc[1][0] += av.y*bv.x; acc[1][1] += av.y*bv.y; acc[1][2] += av.y*bv.z; acc[1][3] += av.y*bv.w;
            if (kk < 31) { av = av2; bv = bv2; }
        }
        if (kt + 1 < nk) {
            store_smem((kt + 1) & 1);
            __syncthreads();
        }
    }
    float sc = 1.0f;
    if (scaled) { float t = g_red[0]; sc = 1.0f / (t * t); }
    int i = i0 + 2*ti, j = j0 + 4*tj;
    #pragma unroll
    for (int r = 0; r < 2; r++)
        #pragma unroll
        for (int c = 0; c < 4; c++)
            C[(size_t)(i + r) * n + j + c] = acc[r][c] * sc;
}

// ---------------- trace ----------------
__global__ void k_trace(const float* __restrict__ m, int n) {
    __shared__ float sh[512];
    int t = threadIdx.x;
    sh[t] = (t < n) ? m[t*n + t] : 0.f;
    __syncthreads();
    for (int off = 256; off > 0; off >>= 1) {
        if (t < off) sh[t] += sh[t + off];
        __syncthreads();
    }
    if (t == 0) g_red[0] = sh[0];
}

// ---------------- Rayleigh: v = P*r, lambda = (v^T S v)/(v^T v) ----------------
__global__ void k_rayleigh(const float* __restrict__ P, const float* __restrict__ S,
                           int n, int slot) {
    __shared__ float v[512];
    __shared__ float r1[512], r2[512];
    int t = threadIdx.x;
    float s = 0.f;
    for (int j = 0; j < n; j++) s += P[t*n + j] * (sinf(0.7331f * j + 0.1234f) + 1.5f);
    v[t] = s;
    __syncthreads();
    float w = 0.f;
    for (int j = 0; j < n; j++) w += S[t*n + j] * v[j];
    r1[t] = v[t] * w;
    r2[t] = v[t] * v[t];
    __syncthreads();
    for (int off = n >> 1; off > 0; off >>= 1) {
        if (t < off) { r1[t] += r1[t+off]; r2[t] += r2[t+off]; }
        __syncthreads();
    }
    if (t == 0) g_scal[slot] = r1[0] / r2[0];
}

__global__ void k_scalars() {
    float tau = 1.0f / (2.0f * (g_scal[0] + 0.1f * g_scal[1]));
    float lam2 = (tau * 0.1f > 0.1f) ? (0.1f / tau) : 0.1f;
    g_scal[2] = tau;
    g_scal[3] = tau * lam2;
}

// ---------------- gradient, 64x64 tile / 4x4 microtile ----------------
// z 0..7  -> G[z] = U[:, z*256:(z+1)*256] @ x[:, same]^T  (split-K over M)
// z == 8  -> G[8] = 0.1 * DtD @ A
// z == 9  -> (block 0,0 only) Hankel-tail convergence of previous iteration's T
__global__ void __launch_bounds__(256) gemm_grad(const float* __restrict__ x, int it) {
    if (g_done) return;
    int z = blockIdx.z;
    int tid = threadIdx.x;

    if (z == 9) {
        if (blockIdx.x != 0 || blockIdx.y != 0) return;
        if (it == 0) return;
        __shared__ float diag[128], r1[128], r2[128];
        int t = tid >> 1, s = tid & 1;
        float sum = 0.f;
        if (t < NTAIL) {
            for (int i = t + 1 + s; i < Ldim; i += 2)
                sum += g_T[i * Mdim + (Mdim + t - i)];
        }
        sum += __shfl_down_sync(0xffffffff, sum, 1, 2);
        if (s == 0 && t < 128) diag[t] = (t < NTAIL) ? sum / (float)(NTAIL - t) : 0.f;
        __syncthreads();
        if (tid < 128) {
            float a = (tid < NTAIL) ? diag[tid] : 0.f;
            float y = (tid < NTAIL) ? g_ytail[tid] : 0.f;
            float d = y - a;
            r1[tid] = d * d;
            r2[tid] = y * y;
        }
        __syncthreads();
        for (int off = 64; off > 0; off >>= 1) {
            if (tid < off) { r1[tid] += r1[tid + off]; r2[tid] += r2[tid + off]; }
            __syncthreads();
        }
        if (tid == 0 && sqrtf(r1[0] / r2[0]) <= 1e-5f) g_done = 1;
        if (tid < NTAIL) g_ytail[tid] = diag[tid];
        return;
    }

    __shared__ __align__(16) float Us[2][32][68];
    __shared__ __align__(16) float Xs[2][32][68];
    int i0 = blockIdx.x * 64, j0 = blockIdx.y * 64;
    int ti = tid >> 4, tj = tid & 15;   // 4*ti rows, 4*tj cols
    int tr = tid >> 5, tc = tid & 31;
    int rr = tid >> 6, cc = tid & 63;
    float acc[4][4] = {};
    int nk = (z < 8) ? 8 : 4;
    float ur[8], xr[8];

    auto load_regs = [&](int kt) {
        if (z < 8) {
            int m0 = z * 256 + kt * 32;
            #pragma unroll
            for (int r = 0; r < 8; r++)
                ur[r] = g_U[(size_t)(i0 + tr + 8*r) * Mdim + m0 + tc];
            #pragma unroll
            for (int r = 0; r < 8; r++)
                xr[r] = x[(size_t)(j0 + tr + 8*r) * Mdim + m0 + tc];
        } else {
            int p0 = kt * 32;
            #pragma unroll
            for (int r = 0; r < 8; r++)
                ur[r] = g_DtD[(i0 + tr + 8*r) * Ldim + p0 + tc];
            #pragma unroll
            for (int r = 0; r < 8; r++)
                xr[r] = g_A[(p0 + rr + 4*r) * Ddim + j0 + cc];
        }
    };
    auto store_smem = [&](int b) {
        #pragma unroll
        for (int r = 0; r < 8; r++) Us[b][tc][tr + 8*r] = ur[r];
        if (z < 8) {
            #pragma unroll
            for (int r = 0; r < 8; r++) Xs[b][tc][tr + 8*r] = xr[r];
        } else {
            #pragma unroll
            for (int r = 0; r < 8; r++) Xs[b][rr + 4*r][cc] = xr[r];
        }
    };

    load_regs(0);
    store_smem(0);
    __syncthreads();
    for (int kt = 0; kt < nk; kt++) {
        int b = kt & 1;
        if (kt + 1 < nk) load_regs(kt + 1);
        float4 av = *(const float4*)&Us[b][0][4*ti];
        float4 bv = *(const float4*)&Xs[b][0][4*tj];
        #pragma unroll
        for (int kk = 0; kk < 32; kk++) {
            float4 av2, bv2;
            if (kk < 31) {
                av2 = *(const float4*)&Us[b][kk+1][4*ti];
                bv2 = *(const float4*)&Xs[b][kk+1][4*tj];
            }
            acc[0][0] += av.x*bv.x; acc[0][1] += av.x*bv.y; acc[0][2] += av.x*bv.z; acc[0][3] += av.x*bv.w;
            acc[1][0] += av.y*bv.x; acc[1][1] += av.y*bv.y; acc[1][2] += av.y*bv.z; acc[1][3] += av.y*bv.w;
            acc[2][0] += av.z*bv.x; acc[2][1] += av.z*bv.y; acc[2][2] += av.z*bv.z; acc[2][3] += av.z*bv.w;
            acc[3][0] += av.w*bv.x; acc[3][1] += av.w*bv.y; acc[3][2] += av.w*bv.z; acc[3][3] += av.w*bv.w;
            if (kk < 31) { av = av2; bv = bv2; }
        }
        if (kt + 1 < nk) {
            store_smem((kt + 1) & 1);
            __syncthreads();
        }
    }
    float sc = (z == 8) ? 0.1f : 1.0f;
    int i = i0 + 4*ti, j = j0 + 4*tj;
    float* outp = &g_G[z][0];
    #pragma unroll
    for (int r = 0; r < 4; r++) {
        float4 v = make_float4(acc[r][0]*sc, acc[r][1]*sc, acc[r][2]*sc, acc[r][3]*sc);
        *(float4*)&outp[(i + r) * Ddim + j] = v;
    }
}

// ---------------- prox + momentum ----------------
__global__ void k_update(float coeff) {
    if (g_done) return;
    float tau = g_scal[2], thr = g_scal[3];
    int idx = blockIdx.x * blockDim.x + threadIdx.x;
    float g = 0.f;
    #pragma unroll
    for (int z = 0; z < NG; z++) g += g_G[z][idx];
    float aold = g_A[idx], b = g_Bm[idx];
    float zv = b - tau * g;
    float az = fabsf(zv) - thr;
    float anew = (az > 0.f) ? copysignf(az, zv) : 0.f;
    g_A[idx]  = anew;
    g_Bm[idx] = aold + coeff * (anew - aold);
}

// ---------------- forward: T = A@x, U = mask*(T - py) (R4-proven, unchanged) ----------------
__global__ void __launch_bounds__(256) gemm_fwd(const float* __restrict__ x,
                                                const float* __restrict__ py,
                                                const float* __restrict__ mask) {
    if (g_done) return;
    __shared__ __align__(16) float As[2][32][34];
    __shared__ __align__(16) float Xs[2][32][68];
    int i0 = blockIdx.x * 32, m0 = blockIdx.y * 64;
    int tid = threadIdx.x;
    int ti = tid >> 4, tj = tid & 15;
    int tr = tid >> 5, tc = tid & 31;
    int rr = tid >> 6, cc = tid & 63;
    float acc[2][4] = {};
    float ar[4], xr[8];

    auto load_regs = [&](int kt) {
        int k0 = kt * 32;
        #pragma unroll
        for (int r = 0; r < 4; r++)
            ar[r] = g_A[(i0 + tr + 8*r) * Ddim + k0 + tc];
        #pragma unroll
        for (int r = 0; r < 8; r++)
            xr[r] = x[(size_t)(k0 + rr + 4*r) * Mdim + m0 + cc];
    };
    auto store_smem = [&](int b) {
        #pragma unroll
        for (int r = 0; r < 4; r++) As[b][tc][tr + 8*r] = ar[r];
        #pragma unroll
        for (int r = 0; r < 8; r++) Xs[b][rr + 4*r][cc] = xr[r];
    };

    load_regs(0);
    store_smem(0);
    __syncthreads();
    for (int kt = 0; kt < 16; kt++) {
        int b = kt & 1;
        if (kt + 1 < 16) load_regs(kt + 1);
        float2 av = *(const float2*)&As[b][0][2*ti];
        float4 bv = *(const float4*)&Xs[b][0][4*tj];
        #pragma unroll
        for (int kk = 0; kk < 32; kk++) {
            float2 av2; float4 bv2;
            if (kk < 31) {
                av2 = *(const float2*)&As[b][kk+1][2*ti];
                bv2 = *(const float4*)&Xs[b][kk+1][4*tj];
            }
            acc[0][0] += av.x*bv.x; acc[0][1] += av.x*bv.y; acc[0][2] += av.x*bv.z; acc[0][3] += av.x*bv.w;
            acc[1][0] += av.y*bv.x; acc[1][1] += av.y*bv.y; acc[1][2] += av.y*bv.z; acc[1][3] += av.y*bv.w;
            if (kk < 31) { av = av2; bv = bv2; }
        }
        if (kt + 1 < 16) {
            store_smem((kt + 1) & 1);
            __syncthreads();
        }
    }
    #pragma unroll
    for (int r = 0; r < 2; r++) {
        int i = i0 + 2*ti + r;
        #pragma unroll
        for (int c = 0; c < 4; c++) {
            int m = m0 + 4*tj + c;
            size_t o = (size_t)i * Mdim + m;
            float t = acc[r][c];
            g_T[o] = t;
            g_U[o] = mask[o] * (t - py[o]);
        }
    }
}

// ---------------- output: (A@x, A) ----------------
__global__ void k_output(float* __restrict__ out, int out_size) {
    int idx = blockIdx.x * blockDim.x + threadIdx.x;
    if (idx >= out_size) return;
    if (idx < Ldim*Mdim) out[idx] = g_T[idx];
    else if (idx < Ldim*Mdim + Ldim*Ddim) out[idx] = g_A[idx - Ldim*Mdim];
}

extern "C" void kernel_launch(void* const* d_in, const int* in_sizes, int n_in,
                              void* d_out, int out_size) {
    const float* x    = (const float*)d_in[0];
    const float* py   = (const float*)d_in[1];
    const float* mask = (const float*)d_in[2];
    const float* y0   = (const float*)d_in[3];
    float* outp = (float*)d_out;

    void *pS, *pP0, *pP1, *pDtD, *pQ0, *pQ1;
    cudaGetSymbolAddress(&pS,   g_S);
    cudaGetSymbolAddress(&pP0,  g_P0);
    cudaGetSymbolAddress(&pP1,  g_P1);
    cudaGetSymbolAddress(&pDtD, g_DtD);
    cudaGetSymbolAddress(&pQ0,  g_Q0);
    cudaGetSymbolAddress(&pQ1,  g_Q1);

    k_init<<<(Ldim*Mdim + 255)/256, 256>>>(mask, py, y0);
    k_delta<<<(Ldim*Ldim + 255)/256, 256>>>();
    k_dtd<<<(Ldim*Ldim + 255)/256, 256>>>();

    // maxeig(x x^T): S = x x^T, then 10 trace-normalized squarings + Rayleigh
    gemm_sq<<<dim3(16, 8), 256>>>(x, (float*)pS, Ddim, Mdim, 0);
    k_trace<<<1, 512>>>((const float*)pS, Ddim);
    {
        float* bufs[2] = { (float*)pP0, (float*)pP1 };
        const float* cur = (const float*)pS;
        for (int i = 0; i < 10; i++) {
            float* nxt = bufs[i & 1];
            gemm_sq<<<dim3(16, 8), 256>>>(cur, nxt, Ddim, Ddim, 1);
            k_trace<<<1, 512>>>(nxt, Ddim);
            cur = nxt;
        }
        k_rayleigh<<<1, Ddim>>>(cur, (const float*)pS, Ddim, 0);
    }

    // maxeig(DtD): 4 trace-normalized squarings + Rayleigh (cluster-averaged; its
    // term contributes ~0.03% to tau, validated in R10)
    k_trace<<<1, 512>>>((const float*)pDtD, Ldim);
    {
        float* bufs[2] = { (float*)pQ0, (float*)pQ1 };
        const float* cur = (const float*)pDtD;
        for (int i = 0; i < 4; i++) {
            float* nxt = bufs[i & 1];
            gemm_sq<<<dim3(4, 2), 256>>>(cur, nxt, Ldim, Ldim, 1);
            k_trace<<<1, 512>>>(nxt, Ldim);
            cur = nxt;
        }
        k_rayleigh<<<1, Ldim>>>(cur, (const float*)pDtD, Ldim, 1);
    }

    k_scalars<<<1, 1>>>();

    // FISTA loop: 3 kernels/iter, device-side early exit
    float a = 1.0f;
    for (int it = 0; it < 200; it++) {
        float anew = (1.0f + sqrtf(1.0f + 4.0f * a * a)) * 0.5f;
        float coeff = (a - 1.0f) / anew;
        a = anew;
        gemm_grad<<<dim3(2, 8, 10), 256>>>(x, it);
        k_update<<<(Ldim*Ddim)/256, 256>>>(coeff);
        gemm_fwd<<<dim3(Ldim/32, Mdim/64), 256>>>(x, py, mask);
    }

    k_output<<<(out_size + 255)/256, 256>>>(outp, out_size);
}